// round 8
// baseline (speedup 1.0000x reference)
#include <cuda_runtime.h>
#include <math.h>

#define B_  2
#define T_  2048
#define D_  1024
#define H_  16
#define HD  64
#define M_  (B_*T_)          // 4096
#define WIN 64               // keys j in [i, i+64] (65 keys)
#define QT  32               // queries per attention block
#define KROWS (QT + WIN)     // 96 key rows per tile

// Scratch (allocation-free rule: __device__ globals)
__device__ float g_q[B_*H_*T_*HD];
__device__ float g_k[B_*H_*T_*HD];
__device__ float g_v[B_*H_*T_*HD];
__device__ float g_ao[B_*T_*D_];   // attention output, [B][T][H*hd]

// ---------------------------------------------------------------------------
// NT SGEMM: C[m,n] = sum_k A[m,k] * Bm[n,k] + bias[n]
// mode 0: A = x, scatter epilogue into g_q/g_k/g_v  (N = 3072)
// mode 1: A = g_ao, plain epilogue into C           (N = 1024)
// Tiles: 128x128x8, 256 threads, 8x8 per-thread microtile (4+64 split).
// Double-buffered smem, one __syncthreads per K-tile.
// ---------------------------------------------------------------------------
__global__ __launch_bounds__(256) void sgemm_nt(
    const float* __restrict__ A, const float* __restrict__ Bm,
    const float* __restrict__ bias, float* __restrict__ C,
    int K, int mode)
{
    __shared__ float As[2][8][128];
    __shared__ float Bs[2][8][128];

    const float* Ap = (mode == 1) ? g_ao : A;

    const int tid   = threadIdx.x;
    const int mbase = blockIdx.y * 128;
    const int nbase = blockIdx.x * 128;

    const int lrow = tid >> 1;          // 0..127
    const int lseg = (tid & 1) * 4;     // 0 or 4

    const float* aptr = Ap + (size_t)(mbase + lrow) * K + lseg;
    const float* bptr = Bm + (size_t)(nbase + lrow) * K + lseg;

    float acc[8][8];
#pragma unroll
    for (int i = 0; i < 8; i++)
#pragma unroll
        for (int j = 0; j < 8; j++) acc[i][j] = 0.f;

    const int ty = tid >> 4;   // 0..15
    const int tx = tid & 15;   // 0..15

    const int ntiles = K >> 3;

    // preload tile 0
    float4 av = *(const float4*)(aptr);
    float4 bv = *(const float4*)(bptr);
    As[0][lseg + 0][lrow] = av.x;  As[0][lseg + 1][lrow] = av.y;
    As[0][lseg + 2][lrow] = av.z;  As[0][lseg + 3][lrow] = av.w;
    Bs[0][lseg + 0][lrow] = bv.x;  Bs[0][lseg + 1][lrow] = bv.y;
    Bs[0][lseg + 2][lrow] = bv.z;  Bs[0][lseg + 3][lrow] = bv.w;
    __syncthreads();

    for (int t = 0; t < ntiles; t++) {
        const int buf = t & 1;
        const bool has_next = (t + 1 < ntiles);
        if (has_next) {
            av = *(const float4*)(aptr + (t + 1) * 8);
            bv = *(const float4*)(bptr + (t + 1) * 8);
        }
#pragma unroll
        for (int kk = 0; kk < 8; kk++) {
            float4 a0 = *(const float4*)&As[buf][kk][ty * 4];
            float4 a1 = *(const float4*)&As[buf][kk][ty * 4 + 64];
            float4 b0 = *(const float4*)&Bs[buf][kk][tx * 4];
            float4 b1 = *(const float4*)&Bs[buf][kk][tx * 4 + 64];
            float af[8] = {a0.x, a0.y, a0.z, a0.w, a1.x, a1.y, a1.z, a1.w};
            float bf[8] = {b0.x, b0.y, b0.z, b0.w, b1.x, b1.y, b1.z, b1.w};
#pragma unroll
            for (int i = 0; i < 8; i++)
#pragma unroll
                for (int j = 0; j < 8; j++)
                    acc[i][j] = fmaf(af[i], bf[j], acc[i][j]);
        }
        if (has_next) {
            const int nb = buf ^ 1;
            As[nb][lseg + 0][lrow] = av.x;  As[nb][lseg + 1][lrow] = av.y;
            As[nb][lseg + 2][lrow] = av.z;  As[nb][lseg + 3][lrow] = av.w;
            Bs[nb][lseg + 0][lrow] = bv.x;  Bs[nb][lseg + 1][lrow] = bv.y;
            Bs[nb][lseg + 2][lrow] = bv.z;  Bs[nb][lseg + 3][lrow] = bv.w;
            __syncthreads();
        }
    }

    if (mode == 0) {
#pragma unroll
        for (int i = 0; i < 8; i++) {
            const int mr = mbase + ty * 4 + (i & 3) + (i >> 2) * 64;
            const int bb = mr >> 11;          // / T_
            const int t  = mr & (T_ - 1);
#pragma unroll
            for (int j = 0; j < 8; j++) {
                const int nc = nbase + tx * 4 + (j & 3) + (j >> 2) * 64;
                const float v = acc[i][j] + bias[nc];
                const int part = nc >> 10;
                const int h    = (nc >> 6) & (H_ - 1);
                const int d    = nc & (HD - 1);
                float* dst = (part == 0) ? g_q : (part == 1) ? g_k : g_v;
                dst[(((size_t)bb * H_ + h) * T_ + t) * HD + d] = v;
            }
        }
    } else {
#pragma unroll
        for (int i = 0; i < 8; i++) {
            const int mr = mbase + ty * 4 + (i & 3) + (i >> 2) * 64;
#pragma unroll
            for (int j = 0; j < 8; j++) {
                const int nc = nbase + tx * 4 + (j & 3) + (j >> 2) * 64;
                C[(size_t)mr * D_ + nc] = acc[i][j] + bias[nc];
            }
        }
    }
}

// ---------------------------------------------------------------------------
// Sliding-window attention.
// grid = B*H*(T/QT), block = 256 (8 warps). Warp handles one query at a time.
// Keys for query i: j in [i, min(i+WIN, T-1)].
// ---------------------------------------------------------------------------
__global__ __launch_bounds__(256) void attn_kernel()
{
    __shared__ float Ks[KROWS][HD];
    __shared__ float Vs[KROWS][HD];

    const int ntiles = T_ / QT;
    const int qt = blockIdx.x % ntiles;
    const int bh = blockIdx.x / ntiles;    // b*H + h
    const int base = qt * QT;

    const float* kptr = g_k + (size_t)bh * T_ * HD;
    const float* vptr = g_v + (size_t)bh * T_ * HD;

    // load KROWS rows of K and V (float4)
    for (int idx = threadIdx.x; idx < KROWS * (HD / 4); idx += 256) {
        const int row = idx >> 4;          // /16
        const int c4  = idx & 15;
        const int trow = base + row;
        float4 kv = make_float4(0.f, 0.f, 0.f, 0.f);
        float4 vv = kv;
        if (trow < T_) {
            kv = *(const float4*)(kptr + (size_t)trow * HD + c4 * 4);
            vv = *(const float4*)(vptr + (size_t)trow * HD + c4 * 4);
        }
        *(float4*)&Ks[row][c4 * 4] = kv;
        *(float4*)&Vs[row][c4 * 4] = vv;
    }
    __syncthreads();

    const int warp = threadIdx.x >> 5;
    const int lane = threadIdx.x & 31;
    const float scale = 0.125f;            // hd^-0.5 = 1/8

    for (int qi = warp; qi < QT; qi += 8) {
        const int i = base + qi;
        const float* qrow = g_q + ((size_t)bh * T_ + i) * HD;
        const float q0 = qrow[lane];
        const float q1 = qrow[lane + 32];

        float m = -1e30f, l = 0.f, a0 = 0.f, a1 = 0.f;
#pragma unroll 4
        for (int jj = 0; jj <= WIN; jj++) {
            const int j = i + jj;
            if (j >= T_) break;
            const int r = qi + jj;
            float s = q0 * Ks[r][lane] + q1 * Ks[r][lane + 32];
#pragma unroll
            for (int off = 16; off; off >>= 1)
                s += __shfl_xor_sync(0xffffffffu, s, off);
            s *= scale;
            const float mn   = fmaxf(m, s);
            const float corr = __expf(m - mn);
            const float p    = __expf(s - mn);
            l  = l  * corr + p;
            a0 = a0 * corr + p * Vs[r][lane];
            a1 = a1 * corr + p * Vs[r][lane + 32];
            m = mn;
        }
        const float inv = 1.f / l;
        const int bb = bh >> 4;            // / H_
        const int h  = bh & (H_ - 1);
        float* out = g_ao + ((size_t)bb * T_ + i) * D_ + h * HD;
        out[lane]      = a0 * inv;
        out[lane + 32] = a1 * inv;
    }
}

// ---------------------------------------------------------------------------
extern "C" void kernel_launch(void* const* d_in, const int* in_sizes, int n_in,
                              void* d_out, int out_size)
{
    const float* x     = (const float*)d_in[0];
    const float* w_qkv = (const float*)d_in[1];
    const float* b_qkv = (const float*)d_in[2];
    const float* w_out = (const float*)d_in[3];
    const float* b_out = (const float*)d_in[4];
    float* out = (float*)d_out;

    // 1) QKV projection: M=4096, N=3072, K=1024
    {
        dim3 grid(3072 / 128, M_ / 128);
        sgemm_nt<<<grid, 256>>>(x, w_qkv, b_qkv, nullptr, D_, 0);
    }
    // 2) sliding-window attention
    {
        attn_kernel<<<B_ * H_ * (T_ / QT), 256>>>();
    }
    // 3) output projection: M=4096, N=1024, K=1024
    {
        dim3 grid(D_ / 128, M_ / 128);
        sgemm_nt<<<grid, 256>>>(nullptr, w_out, b_out, out, D_, 1);
    }
}

// round 16
// speedup vs baseline: 1.5430x; 1.5430x over previous
#include <cuda_runtime.h>
#include <cuda_bf16.h>
#include <mma.h>
#include <stdint.h>

using namespace nvcuda;

#define B_  2
#define T_  2048
#define D_  1024
#define H_  16
#define HD  64
#define M_  (B_*T_)          // 4096
#define WIN 64
#define QT  32
#define KROWS (QT + WIN)
#define KDIM 1024
#define LDT 24               // smem leading dim (16 + 8 pad) for bf16 tiles

// ---- scratch (__device__ globals; allocation-free rule) ----
__device__ float g_q[B_*H_*T_*HD];
__device__ float g_k[B_*H_*T_*HD];
__device__ float g_v[B_*H_*T_*HD];
__device__ float g_ao[M_*D_];

__device__ __align__(16) __nv_bfloat16 g_x_hi [M_*D_];
__device__ __align__(16) __nv_bfloat16 g_x_lo [M_*D_];
__device__ __align__(16) __nv_bfloat16 g_wq_hi[3*D_*D_];
__device__ __align__(16) __nv_bfloat16 g_wq_lo[3*D_*D_];
__device__ __align__(16) __nv_bfloat16 g_wo_hi[D_*D_];
__device__ __align__(16) __nv_bfloat16 g_wo_lo[D_*D_];
__device__ __align__(16) __nv_bfloat16 g_ao_hi[M_*D_];
__device__ __align__(16) __nv_bfloat16 g_ao_lo[M_*D_];

__device__ float g_bq_rep[16*3072];   // b_qkv replicated over 16 rows
__device__ float g_bo_rep[16*1024];   // b_out replicated over 16 rows

// ---- convert fp32 -> bf16 hi/lo split ----
__global__ __launch_bounds__(256) void cvt_split(const float* __restrict__ src_ext, int which)
{
    const float* src = (which == 3) ? g_ao : src_ext;
    __nv_bfloat16 *hi, *lo;
    if      (which == 0) { hi = g_x_hi;  lo = g_x_lo;  }
    else if (which == 1) { hi = g_wq_hi; lo = g_wq_lo; }
    else if (which == 2) { hi = g_wo_hi; lo = g_wo_lo; }
    else                 { hi = g_ao_hi; lo = g_ao_lo; }

    const int i = (blockIdx.x * 256 + threadIdx.x) * 4;
    float4 v = *(const float4*)(src + i);
    float vv[4] = {v.x, v.y, v.z, v.w};
    __nv_bfloat16 h[4], l[4];
#pragma unroll
    for (int j = 0; j < 4; j++) {
        h[j] = __float2bfloat16(vv[j]);
        l[j] = __float2bfloat16(vv[j] - __bfloat162float(h[j]));
    }
    *(uint2*)(hi + i) = *(uint2*)h;
    *(uint2*)(lo + i) = *(uint2*)l;
}

// ---- replicate bias over 16 rows (for wmma accumulator init) ----
__global__ __launch_bounds__(256) void rep_bias(const float* __restrict__ b, int which, int n)
{
    const int i = blockIdx.x * 256 + threadIdx.x;
    if (i >= 16 * n) return;
    float* dst = which ? g_bo_rep : g_bq_rep;
    dst[i] = b[i % n];
}

// ---- wmma GEMM: C[128x128/blk] = A(hi+lo) @ B(hi+lo)^T + bias ----
// 3-term split: Ahi*Bhi + Ahi*Blo + Alo*Bhi (fp32 accum).
// mode 0: A = g_x, B = g_wq (N=3072), scatter -> g_q/g_k/g_v (bias-included)
// mode 1: A = g_ao, B = g_wo (N=1024), dense -> C (bias-included)
__global__ __launch_bounds__(256) void gemm_wmma(float* __restrict__ C, int mode)
{
    // tiles: 0 A_hi, 1 A_lo, 2 B_hi, 3 B_lo; double buffered
    __shared__ __nv_bfloat16 sm[2][4][128 * LDT];

    const int tid = threadIdx.x;
    const int wid = tid >> 5;
    const int wm  = wid >> 1;      // 0..3  (32-row slice)
    const int wn  = wid & 1;       // 0..1  (64-col slice)
    const int nbase = blockIdx.x * 128;
    const int mbase = blockIdx.y * 128;

    const __nv_bfloat16 *Ahi, *Alo, *Bhi, *Blo;
    const float* brep;
    int BN;
    if (mode == 0) { Ahi = g_x_hi;  Alo = g_x_lo;  Bhi = g_wq_hi; Blo = g_wq_lo; brep = g_bq_rep; BN = 3072; }
    else           { Ahi = g_ao_hi; Alo = g_ao_lo; Bhi = g_wo_hi; Blo = g_wo_lo; brep = g_bo_rep; BN = 1024; }

    // accumulators init = bias (replicated rows, so any 16 rows give bias per col)
    wmma::fragment<wmma::accumulator, 16, 16, 16, float> acc[2][4];
#pragma unroll
    for (int m = 0; m < 2; m++)
#pragma unroll
        for (int n = 0; n < 4; n++)
            wmma::load_matrix_sync(acc[m][n], brep + nbase + wn * 64 + n * 16, BN, wmma::mem_row_major);

    // per-thread load role: one 16B unit per tile per k-step
    const int lrow = tid >> 1;          // 0..127
    const int half = tid & 1;           // 0 or 1 (k offset 0 / 8)
    const __nv_bfloat16* srcs[4] = {
        Ahi + (size_t)(mbase + lrow) * KDIM + half * 8,
        Alo + (size_t)(mbase + lrow) * KDIM + half * 8,
        Bhi + (size_t)(nbase + lrow) * KDIM + half * 8,
        Blo + (size_t)(nbase + lrow) * KDIM + half * 8 };
    const int sm_off = lrow * LDT + half * 8;

    const int NK = KDIM / 16;   // 64 k-steps

    // preload k-step 0
    {
        uint4 v0 = *(const uint4*)srcs[0];
        uint4 v1 = *(const uint4*)srcs[1];
        uint4 v2 = *(const uint4*)srcs[2];
        uint4 v3 = *(const uint4*)srcs[3];
        *(uint4*)&sm[0][0][sm_off] = v0;
        *(uint4*)&sm[0][1][sm_off] = v1;
        *(uint4*)&sm[0][2][sm_off] = v2;
        *(uint4*)&sm[0][3][sm_off] = v3;
    }
    __syncthreads();

    for (int kt = 0; kt < NK; kt++) {
        const int buf = kt & 1;
        uint4 p0, p1, p2, p3;
        const bool has_next = (kt + 1 < NK);
        if (has_next) {
            const int ko = (kt + 1) * 16;
            p0 = *(const uint4*)(srcs[0] + ko);
            p1 = *(const uint4*)(srcs[1] + ko);
            p2 = *(const uint4*)(srcs[2] + ko);
            p3 = *(const uint4*)(srcs[3] + ko);
        }

        wmma::fragment<wmma::matrix_a, 16, 16, 16, __nv_bfloat16, wmma::row_major> ah[2], al[2];
#pragma unroll
        for (int m = 0; m < 2; m++) {
            wmma::load_matrix_sync(ah[m], &sm[buf][0][(wm * 32 + m * 16) * LDT], LDT);
            wmma::load_matrix_sync(al[m], &sm[buf][1][(wm * 32 + m * 16) * LDT], LDT);
        }
#pragma unroll
        for (int n = 0; n < 4; n++) {
            wmma::fragment<wmma::matrix_b, 16, 16, 16, __nv_bfloat16, wmma::col_major> bh, bl;
            wmma::load_matrix_sync(bh, &sm[buf][2][(wn * 64 + n * 16) * LDT], LDT);
            wmma::load_matrix_sync(bl, &sm[buf][3][(wn * 64 + n * 16) * LDT], LDT);
#pragma unroll
            for (int m = 0; m < 2; m++) {
                wmma::mma_sync(acc[m][n], ah[m], bh, acc[m][n]);
                wmma::mma_sync(acc[m][n], ah[m], bl, acc[m][n]);
                wmma::mma_sync(acc[m][n], al[m], bh, acc[m][n]);
            }
        }

        if (has_next) {
            const int nb = buf ^ 1;
            *(uint4*)&sm[nb][0][sm_off] = p0;
            *(uint4*)&sm[nb][1][sm_off] = p1;
            *(uint4*)&sm[nb][2][sm_off] = p2;
            *(uint4*)&sm[nb][3][sm_off] = p3;
            __syncthreads();
        }
    }

    // epilogue: direct frag stores
#pragma unroll
    for (int m = 0; m < 2; m++) {
        const int mr = mbase + wm * 32 + m * 16;
#pragma unroll
        for (int n = 0; n < 4; n++) {
            const int n0 = nbase + wn * 64 + n * 16;
            if (mode == 0) {
                const int part = n0 >> 10;
                const int h    = (n0 >> 6) & (H_ - 1);
                const int d0   = n0 & (HD - 1);
                const int bb   = mr >> 11;
                const int t0   = mr & (T_ - 1);
                float* dst = ((part == 0) ? g_q : (part == 1) ? g_k : g_v)
                             + (((size_t)bb * H_ + h) * T_ + t0) * HD + d0;
                wmma::store_matrix_sync(dst, acc[m][n], HD, wmma::mem_row_major);
            } else {
                wmma::store_matrix_sync(C + (size_t)mr * D_ + n0, acc[m][n], D_, wmma::mem_row_major);
            }
        }
    }
}

// ---- sliding-window attention (unchanged from passing baseline) ----
__global__ __launch_bounds__(256) void attn_kernel()
{
    __shared__ float Ks[KROWS][HD];
    __shared__ float Vs[KROWS][HD];

    const int ntiles = T_ / QT;
    const int qt = blockIdx.x % ntiles;
    const int bh = blockIdx.x / ntiles;
    const int base = qt * QT;

    const float* kptr = g_k + (size_t)bh * T_ * HD;
    const float* vptr = g_v + (size_t)bh * T_ * HD;

    for (int idx = threadIdx.x; idx < KROWS * (HD / 4); idx += 256) {
        const int row = idx >> 4;
        const int c4  = idx & 15;
        const int trow = base + row;
        float4 kv = make_float4(0.f, 0.f, 0.f, 0.f);
        float4 vv = kv;
        if (trow < T_) {
            kv = *(const float4*)(kptr + (size_t)trow * HD + c4 * 4);
            vv = *(const float4*)(vptr + (size_t)trow * HD + c4 * 4);
        }
        *(float4*)&Ks[row][c4 * 4] = kv;
        *(float4*)&Vs[row][c4 * 4] = vv;
    }
    __syncthreads();

    const int warp = threadIdx.x >> 5;
    const int lane = threadIdx.x & 31;
    const float scale = 0.125f;

    for (int qi = warp; qi < QT; qi += 8) {
        const int i = base + qi;
        const float* qrow = g_q + ((size_t)bh * T_ + i) * HD;
        const float q0 = qrow[lane];
        const float q1 = qrow[lane + 32];

        float m = -1e30f, l = 0.f, a0 = 0.f, a1 = 0.f;
#pragma unroll 4
        for (int jj = 0; jj <= WIN; jj++) {
            const int j = i + jj;
            if (j >= T_) break;
            const int r = qi + jj;
            float s = q0 * Ks[r][lane] + q1 * Ks[r][lane + 32];
#pragma unroll
            for (int off = 16; off; off >>= 1)
                s += __shfl_xor_sync(0xffffffffu, s, off);
            s *= scale;
            const float mn   = fmaxf(m, s);
            const float corr = __expf(m - mn);
            const float p    = __expf(s - mn);
            l  = l  * corr + p;
            a0 = a0 * corr + p * Vs[r][lane];
            a1 = a1 * corr + p * Vs[r][lane + 32];
            m = mn;
        }
        const float inv = 1.f / l;
        const int bb = bh >> 4;
        const int h  = bh & (H_ - 1);
        float* out = g_ao + ((size_t)bb * T_ + i) * D_ + h * HD;
        out[lane]      = a0 * inv;
        out[lane + 32] = a1 * inv;
    }
}

// ---------------------------------------------------------------------------
extern "C" void kernel_launch(void* const* d_in, const int* in_sizes, int n_in,
                              void* d_out, int out_size)
{
    const float* x     = (const float*)d_in[0];
    const float* w_qkv = (const float*)d_in[1];
    const float* b_qkv = (const float*)d_in[2];
    const float* w_out = (const float*)d_in[3];
    const float* b_out = (const float*)d_in[4];
    float* out = (float*)d_out;

    // split conversions + bias replication
    cvt_split<<<(M_ * D_)   / 1024, 256>>>(x,     0);
    cvt_split<<<(3*D_ * D_) / 1024, 256>>>(w_qkv, 1);
    cvt_split<<<(D_ * D_)   / 1024, 256>>>(w_out, 2);
    rep_bias<<<(16 * 3072 + 255) / 256, 256>>>(b_qkv, 0, 3072);
    rep_bias<<<(16 * 1024 + 255) / 256, 256>>>(b_out, 1, 1024);

    // QKV projection: M=4096, N=3072 (scatter + bias)
    {
        dim3 grid(3072 / 128, M_ / 128);
        gemm_wmma<<<grid, 256>>>(nullptr, 0);
    }
    // sliding-window attention
    attn_kernel<<<B_ * H_ * (T_ / QT), 256>>>();

    // convert attention output, then out projection: M=4096, N=1024
    cvt_split<<<(M_ * D_) / 1024, 256>>>(nullptr, 3);
    {
        dim3 grid(D_ / 128, M_ / 128);
        gemm_wmma<<<grid, 256>>>(out, 1);
    }
}

// round 17
// speedup vs baseline: 1.5456x; 1.0017x over previous
#include <cuda_runtime.h>
#include <cuda_bf16.h>
#include <mma.h>
#include <stdint.h>

using namespace nvcuda;

#define B_  2
#define T_  2048
#define D_  1024
#define H_  16
#define HD  64
#define M_  (B_*T_)          // 4096
#define WIN 64
#define QT  32
#define KROWS (QT + WIN)
#define KDIM 1024
#define LDT 24               // smem leading dim (16 + 8 pad) for bf16 tiles
#define NSTAGE 4
#define TILE_ELEMS (128 * LDT)

// ---- scratch (__device__ globals; allocation-free rule) ----
__device__ float g_q[B_*H_*T_*HD];
__device__ float g_k[B_*H_*T_*HD];
__device__ float g_v[B_*H_*T_*HD];

__device__ __align__(16) __nv_bfloat16 g_x_hi [M_*D_];
__device__ __align__(16) __nv_bfloat16 g_x_lo [M_*D_];
__device__ __align__(16) __nv_bfloat16 g_wq_hi[3*D_*D_];
__device__ __align__(16) __nv_bfloat16 g_wq_lo[3*D_*D_];
__device__ __align__(16) __nv_bfloat16 g_wo_hi[D_*D_];
__device__ __align__(16) __nv_bfloat16 g_wo_lo[D_*D_];
__device__ __align__(16) __nv_bfloat16 g_ao_hi[M_*D_];
__device__ __align__(16) __nv_bfloat16 g_ao_lo[M_*D_];

__device__ float g_bq_rep[16*3072];   // b_qkv replicated over 16 rows
__device__ float g_bo_rep[16*1024];   // b_out replicated over 16 rows

__device__ __forceinline__ uint32_t smem_u32(const void* p) {
    uint32_t a;
    asm("{ .reg .u64 t; cvta.to.shared.u64 t, %1; cvt.u32.u64 %0, t; }" : "=r"(a) : "l"(p));
    return a;
}
#define CP_ASYNC16(saddr, gptr) \
    asm volatile("cp.async.cg.shared.global [%0], [%1], 16;" :: "r"(saddr), "l"(gptr))
#define CP_COMMIT() asm volatile("cp.async.commit_group;" ::: "memory")
#define CP_WAIT2()  asm volatile("cp.async.wait_group 2;" ::: "memory")

// ---- convert fp32 -> bf16 hi/lo split (inputs only) ----
__global__ __launch_bounds__(256) void cvt_split(const float* __restrict__ src, int which)
{
    __nv_bfloat16 *hi, *lo;
    if      (which == 0) { hi = g_x_hi;  lo = g_x_lo;  }
    else if (which == 1) { hi = g_wq_hi; lo = g_wq_lo; }
    else                 { hi = g_wo_hi; lo = g_wo_lo; }

    const int i = (blockIdx.x * 256 + threadIdx.x) * 4;
    float4 v = *(const float4*)(src + i);
    float vv[4] = {v.x, v.y, v.z, v.w};
    __nv_bfloat16 h[4], l[4];
#pragma unroll
    for (int j = 0; j < 4; j++) {
        h[j] = __float2bfloat16(vv[j]);
        l[j] = __float2bfloat16(vv[j] - __bfloat162float(h[j]));
    }
    *(uint2*)(hi + i) = *(uint2*)h;
    *(uint2*)(lo + i) = *(uint2*)l;
}

// ---- replicate bias over 16 rows (for wmma accumulator init) ----
__global__ __launch_bounds__(256) void rep_bias(const float* __restrict__ b, int which, int n)
{
    const int i = blockIdx.x * 256 + threadIdx.x;
    if (i >= 16 * n) return;
    float* dst = which ? g_bo_rep : g_bq_rep;
    dst[i] = b[i % n];
}

// ---- wmma GEMM, 4-stage cp.async pipeline ----
// 3-term split: Ahi*Bhi + Ahi*Blo + Alo*Bhi (fp32 accum), bias folded into acc init.
// mode 0: A = g_x, B = g_wq (N=3072), scatter -> g_q/g_k/g_v
// mode 1: A = g_ao, B = g_wo (N=1024), dense -> C
__global__ __launch_bounds__(256) void gemm_wmma(float* __restrict__ C, int mode)
{
    extern __shared__ __nv_bfloat16 smem[];   // [NSTAGE][4][128*LDT]

    const int tid = threadIdx.x;
    const int wid = tid >> 5;
    const int wm  = wid >> 1;      // 0..3  (32-row slice)
    const int wn  = wid & 1;       // 0..1  (64-col slice)
    const int nbase = blockIdx.x * 128;
    const int mbase = blockIdx.y * 128;

    const __nv_bfloat16 *Ahi, *Alo, *Bhi, *Blo;
    const float* brep;
    int BN;
    if (mode == 0) { Ahi = g_x_hi;  Alo = g_x_lo;  Bhi = g_wq_hi; Blo = g_wq_lo; brep = g_bq_rep; BN = 3072; }
    else           { Ahi = g_ao_hi; Alo = g_ao_lo; Bhi = g_wo_hi; Blo = g_wo_lo; brep = g_bo_rep; BN = 1024; }

    // accumulators init = bias (replicated rows -> per-column bias)
    wmma::fragment<wmma::accumulator, 16, 16, 16, float> acc[2][4];
#pragma unroll
    for (int m = 0; m < 2; m++)
#pragma unroll
        for (int n = 0; n < 4; n++)
            wmma::load_matrix_sync(acc[m][n], brep + nbase + wn * 64 + n * 16, BN, wmma::mem_row_major);

    // per-thread copy role: one 16B unit per tile per k-step
    const int lrow = tid >> 1;          // 0..127
    const int half = tid & 1;           // k offset 0 / 8
    const __nv_bfloat16* srcs[4] = {
        Ahi + (size_t)(mbase + lrow) * KDIM + half * 8,
        Alo + (size_t)(mbase + lrow) * KDIM + half * 8,
        Bhi + (size_t)(nbase + lrow) * KDIM + half * 8,
        Blo + (size_t)(nbase + lrow) * KDIM + half * 8 };
    const int sm_off = lrow * LDT + half * 8;
    const uint32_t sb = smem_u32(smem);

    const int NK = KDIM / 16;   // 64 k-steps

    // prefill stages 0..NSTAGE-2
#pragma unroll
    for (int s = 0; s < NSTAGE - 1; s++) {
#pragma unroll
        for (int t = 0; t < 4; t++) {
            uint32_t dstp = sb + ((s * 4 + t) * TILE_ELEMS + sm_off) * 2;
            CP_ASYNC16(dstp, srcs[t] + s * 16);
        }
        CP_COMMIT();
    }

    for (int kt = 0; kt < NK; kt++) {
        const int buf = kt & (NSTAGE - 1);
        CP_WAIT2();            // stage kt resident (<=2 younger groups pending)
        __syncthreads();

        const int nk = kt + NSTAGE - 1;
        if (nk < NK) {
            const int nb = nk & (NSTAGE - 1);
#pragma unroll
            for (int t = 0; t < 4; t++) {
                uint32_t dstp = sb + ((nb * 4 + t) * TILE_ELEMS + sm_off) * 2;
                CP_ASYNC16(dstp, srcs[t] + nk * 16);
            }
        }
        CP_COMMIT();           // commit (possibly empty) to keep group accounting uniform

        const __nv_bfloat16* st = smem + buf * 4 * TILE_ELEMS;
        wmma::fragment<wmma::matrix_a, 16, 16, 16, __nv_bfloat16, wmma::row_major> ah[2], al[2];
#pragma unroll
        for (int m = 0; m < 2; m++) {
            wmma::load_matrix_sync(ah[m], st + 0 * TILE_ELEMS + (wm * 32 + m * 16) * LDT, LDT);
            wmma::load_matrix_sync(al[m], st + 1 * TILE_ELEMS + (wm * 32 + m * 16) * LDT, LDT);
        }
#pragma unroll
        for (int n = 0; n < 4; n++) {
            wmma::fragment<wmma::matrix_b, 16, 16, 16, __nv_bfloat16, wmma::col_major> bh, bl;
            wmma::load_matrix_sync(bh, st + 2 * TILE_ELEMS + (wn * 64 + n * 16) * LDT, LDT);
            wmma::load_matrix_sync(bl, st + 3 * TILE_ELEMS + (wn * 64 + n * 16) * LDT, LDT);
#pragma unroll
            for (int m = 0; m < 2; m++) {
                wmma::mma_sync(acc[m][n], ah[m], bh, acc[m][n]);
                wmma::mma_sync(acc[m][n], ah[m], bl, acc[m][n]);
                wmma::mma_sync(acc[m][n], al[m], bh, acc[m][n]);
            }
        }
    }

    // epilogue: direct frag stores
#pragma unroll
    for (int m = 0; m < 2; m++) {
        const int mr = mbase + wm * 32 + m * 16;
#pragma unroll
        for (int n = 0; n < 4; n++) {
            const int n0 = nbase + wn * 64 + n * 16;
            if (mode == 0) {
                const int part = n0 >> 10;
                const int h    = (n0 >> 6) & (H_ - 1);
                const int d0   = n0 & (HD - 1);
                const int bb   = mr >> 11;
                const int t0   = mr & (T_ - 1);
                float* dst = ((part == 0) ? g_q : (part == 1) ? g_k : g_v)
                             + (((size_t)bb * H_ + h) * T_ + t0) * HD + d0;
                wmma::store_matrix_sync(dst, acc[m][n], HD, wmma::mem_row_major);
            } else {
                wmma::store_matrix_sync(C + (size_t)mr * D_ + n0, acc[m][n], D_, wmma::mem_row_major);
            }
        }
    }
}

// ---- sliding-window attention; writes bf16 hi/lo split directly ----
__global__ __launch_bounds__(256) void attn_kernel()
{
    __shared__ float Ks[KROWS][HD];
    __shared__ float Vs[KROWS][HD];

    const int ntiles = T_ / QT;
    const int qt = blockIdx.x % ntiles;
    const int bh = blockIdx.x / ntiles;
    const int base = qt * QT;

    const float* kptr = g_k + (size_t)bh * T_ * HD;
    const float* vptr = g_v + (size_t)bh * T_ * HD;

    for (int idx = threadIdx.x; idx < KROWS * (HD / 4); idx += 256) {
        const int row = idx >> 4;
        const int c4  = idx & 15;
        const int trow = base + row;
        float4 kv = make_float4(0.f, 0.f, 0.f, 0.f);
        float4 vv = kv;
        if (trow < T_) {
            kv = *(const float4*)(kptr + (size_t)trow * HD + c4 * 4);
            vv = *(const float4*)(vptr + (size_t)trow * HD + c4 * 4);
        }
        *(float4*)&Ks[row][c4 * 4] = kv;
        *(float4*)&Vs[row][c4 * 4] = vv;
    }
    __syncthreads();

    const int warp = threadIdx.x >> 5;
    const int lane = threadIdx.x & 31;
    const float scale = 0.125f;

    for (int qi = warp; qi < QT; qi += 8) {
        const int i = base + qi;
        const float* qrow = g_q + ((size_t)bh * T_ + i) * HD;
        const float q0 = qrow[lane];
        const float q1 = qrow[lane + 32];

        float m = -1e30f, l = 0.f, a0 = 0.f, a1 = 0.f;
#pragma unroll 4
        for (int jj = 0; jj <= WIN; jj++) {
            const int j = i + jj;
            if (j >= T_) break;
            const int r = qi + jj;
            float s = q0 * Ks[r][lane] + q1 * Ks[r][lane + 32];
#pragma unroll
            for (int off = 16; off; off >>= 1)
                s += __shfl_xor_sync(0xffffffffu, s, off);
            s *= scale;
            const float mn   = fmaxf(m, s);
            const float corr = __expf(m - mn);
            const float p    = __expf(s - mn);
            l  = l  * corr + p;
            a0 = a0 * corr + p * Vs[r][lane];
            a1 = a1 * corr + p * Vs[r][lane + 32];
            m = mn;
        }
        const float inv = 1.f / l;
        const int bb = bh >> 4;
        const int h  = bh & (H_ - 1);
        const size_t ob = ((size_t)bb * T_ + i) * D_ + h * HD;

        const float o0 = a0 * inv;
        const float o1 = a1 * inv;
        const __nv_bfloat16 h0 = __float2bfloat16(o0);
        const __nv_bfloat16 h1 = __float2bfloat16(o1);
        g_ao_hi[ob + lane]      = h0;
        g_ao_hi[ob + lane + 32] = h1;
        g_ao_lo[ob + lane]      = __float2bfloat16(o0 - __bfloat162float(h0));
        g_ao_lo[ob + lane + 32] = __float2bfloat16(o1 - __bfloat162float(h1));
    }
}

// ---------------------------------------------------------------------------
extern "C" void kernel_launch(void* const* d_in, const int* in_sizes, int n_in,
                              void* d_out, int out_size)
{
    const float* x     = (const float*)d_in[0];
    const float* w_qkv = (const float*)d_in[1];
    const float* b_qkv = (const float*)d_in[2];
    const float* w_out = (const float*)d_in[3];
    const float* b_out = (const float*)d_in[4];
    float* out = (float*)d_out;

    const int SMEM_GEMM = NSTAGE * 4 * TILE_ELEMS * 2;   // 98304 B
    cudaFuncSetAttribute(gemm_wmma, cudaFuncAttributeMaxDynamicSharedMemorySize, SMEM_GEMM);

    // split conversions + bias replication
    cvt_split<<<(M_ * D_)   / 1024, 256>>>(x,     0);
    cvt_split<<<(3*D_ * D_) / 1024, 256>>>(w_qkv, 1);
    cvt_split<<<(D_ * D_)   / 1024, 256>>>(w_out, 2);
    rep_bias<<<(16 * 3072 + 255) / 256, 256>>>(b_qkv, 0, 3072);
    rep_bias<<<(16 * 1024 + 255) / 256, 256>>>(b_out, 1, 1024);

    // QKV projection: M=4096, N=3072 (scatter + bias)
    {
        dim3 grid(3072 / 128, M_ / 128);
        gemm_wmma<<<grid, 256, SMEM_GEMM>>>(nullptr, 0);
    }
    // sliding-window attention (emits bf16 hi/lo directly)
    attn_kernel<<<B_ * H_ * (T_ / QT), 256>>>();

    // out projection: M=4096, N=1024
    {
        dim3 grid(D_ / 128, M_ / 128);
        gemm_wmma<<<grid, 256, SMEM_GEMM>>>(out, 1);
    }
}